// round 6
// baseline (speedup 1.0000x reference)
#include <cuda_runtime.h>
#include <cstdint>

// Problem constants
#define BATCH 16
#define SEQQ 2048
#define SEQK 2048
#define HD   128

// Tile config
#define BQ 128          // queries per CTA
#define BK 64           // keys per tile
#define NTHREADS 256    // 8 warps, 16 query rows per warp

// Shared-memory strides (floats), chosen for conflict-free fragment loads
#define QSTR 132        // 132 % 32 == 4  -> bank = 4*quad + qlan (perm)
#define KSTR 132
#define VSTR 136        // 136 % 32 == 8  -> bank = 8*qlan + quad (perm)
#define PSTR 68         // 68 % 32 == 4

#define SQ_OFF 0
#define SK_OFF (BQ*QSTR)                  // 16896
#define SV_OFF (SK_OFF + BK*KSTR)         // 25344
#define SP_OFF (SV_OFF + BK*VSTR)         // 34048
#define SMEM_FLOATS (SP_OFF + BQ*PSTR)    // 42752 floats = 171008 B

__device__ __forceinline__ float to_tf32(float x) {
    uint32_t u;
    asm("cvt.rna.tf32.f32 %0, %1;" : "=r"(u) : "f"(x));
    return __uint_as_float(u);
}

__device__ __forceinline__ void mma_tf32(float c[4],
                                         uint32_t a0, uint32_t a1, uint32_t a2, uint32_t a3,
                                         uint32_t b0, uint32_t b1) {
    asm volatile(
        "mma.sync.aligned.m16n8k8.row.col.f32.tf32.tf32.f32 "
        "{%0,%1,%2,%3}, {%4,%5,%6,%7}, {%8,%9}, {%0,%1,%2,%3};\n"
        : "+f"(c[0]), "+f"(c[1]), "+f"(c[2]), "+f"(c[3])
        : "r"(a0), "r"(a1), "r"(a2), "r"(a3), "r"(b0), "r"(b1));
}

extern __shared__ float smem[];

__global__ void __launch_bounds__(NTHREADS, 1)
attn_tf32_kernel(const float* __restrict__ Qg, const float* __restrict__ Kg,
                 const float* __restrict__ Vg, const int* __restrict__ Lg,
                 float* __restrict__ Og)
{
    const int b    = blockIdx.y;
    const int qt   = blockIdx.x;
    const int tid  = threadIdx.x;
    const int wid  = tid >> 5;
    const int lane = tid & 31;
    const int quad = lane >> 2;   // 0..7 (groupID)
    const int qlan = lane & 3;    // 0..3 (threadID_in_group)

    const int L = Lg[b];                       // >= 1 by construction
    const int ntiles = (L + BK - 1) / BK;

    float* sQ = smem + SQ_OFF;
    float* sK = smem + SK_OFF;
    float* sV = smem + SV_OFF;
    float* sP = smem + SP_OFF;

    const size_t baseQ  = ((size_t)b * SEQQ + (size_t)qt * BQ) * HD;
    const size_t baseKV = (size_t)b * SEQK * HD;
    const float scale = 0.08838834764831843f;  // 1/sqrt(128)

    // ---- load Q tile (BQ x HD), fold in softmax scale, round to tf32 ----
    for (int i = tid; i < BQ * (HD / 4); i += NTHREADS) {
        int row = i >> 5;     // HD/4 = 32
        int c4  = i & 31;
        float4 v = *(const float4*)(Qg + baseQ + (size_t)row * HD + c4 * 4);
        float* dst = sQ + row * QSTR + c4 * 4;
        dst[0] = to_tf32(v.x * scale);
        dst[1] = to_tf32(v.y * scale);
        dst[2] = to_tf32(v.z * scale);
        dst[3] = to_tf32(v.w * scale);
    }

    // per-thread softmax state: rows r0 = wid*16 + quad, r1 = r0 + 8
    float m0 = -1e30f, m1 = -1e30f;
    float l0 = 0.f,    l1 = 0.f;
    float oacc[16][4];
    #pragma unroll
    for (int n = 0; n < 16; n++) {
        oacc[n][0] = 0.f; oacc[n][1] = 0.f; oacc[n][2] = 0.f; oacc[n][3] = 0.f;
    }

    const float* qb = sQ + (wid * 16) * QSTR;
    float* pb = sP + (wid * 16) * PSTR;

    for (int t = 0; t < ntiles; ++t) {
        __syncthreads();   // previous tile fully consumed (sK/sV reusable)

        // ---- load K,V tile (BK x HD) with tf32 rounding ----
        const size_t kvoff = baseKV + (size_t)t * BK * HD;
        for (int i = tid; i < BK * (HD / 4); i += NTHREADS) {
            int row = i >> 5;
            int c4  = i & 31;
            float4 kv = *(const float4*)(Kg + kvoff + (size_t)row * HD + c4 * 4);
            float* dk = sK + row * KSTR + c4 * 4;
            dk[0] = to_tf32(kv.x); dk[1] = to_tf32(kv.y);
            dk[2] = to_tf32(kv.z); dk[3] = to_tf32(kv.w);
            float4 vv = *(const float4*)(Vg + kvoff + (size_t)row * HD + c4 * 4);
            float* dv = sV + row * VSTR + c4 * 4;
            dv[0] = to_tf32(vv.x); dv[1] = to_tf32(vv.y);
            dv[2] = to_tf32(vv.z); dv[3] = to_tf32(vv.w);
        }
        __syncthreads();

        // ---- S = Q * K^T : per-warp 16 x 64, tf32 MMA ----
        float sacc[8][4];
        #pragma unroll
        for (int n = 0; n < 8; n++) {
            sacc[n][0] = 0.f; sacc[n][1] = 0.f; sacc[n][2] = 0.f; sacc[n][3] = 0.f;
        }
        #pragma unroll
        for (int k8 = 0; k8 < 16; k8++) {
            uint32_t a0 = __float_as_uint(qb[(quad    ) * QSTR + k8 * 8 + qlan    ]);
            uint32_t a1 = __float_as_uint(qb[(quad + 8) * QSTR + k8 * 8 + qlan    ]);
            uint32_t a2 = __float_as_uint(qb[(quad    ) * QSTR + k8 * 8 + qlan + 4]);
            uint32_t a3 = __float_as_uint(qb[(quad + 8) * QSTR + k8 * 8 + qlan + 4]);
            #pragma unroll
            for (int n = 0; n < 8; n++) {
                uint32_t b0 = __float_as_uint(sK[(n * 8 + quad) * KSTR + k8 * 8 + qlan    ]);
                uint32_t b1 = __float_as_uint(sK[(n * 8 + quad) * KSTR + k8 * 8 + qlan + 4]);
                mma_tf32(sacc[n], a0, a1, a2, a3, b0, b1);
            }
        }

        // ---- mask trailing keys in the final (partial) tile ----
        const int lim = L - t * BK;
        if (lim < BK) {
            #pragma unroll
            for (int n = 0; n < 8; n++) {
                int c = n * 8 + 2 * qlan;
                if (c     >= lim) { sacc[n][0] = -1e30f; sacc[n][2] = -1e30f; }
                if (c + 1 >= lim) { sacc[n][1] = -1e30f; sacc[n][3] = -1e30f; }
            }
        }

        // ---- online softmax (rows r0, r1 per thread; quad = same rows) ----
        float tm0 = -1e30f, tm1 = -1e30f;
        #pragma unroll
        for (int n = 0; n < 8; n++) {
            tm0 = fmaxf(tm0, fmaxf(sacc[n][0], sacc[n][1]));
            tm1 = fmaxf(tm1, fmaxf(sacc[n][2], sacc[n][3]));
        }
        tm0 = fmaxf(tm0, __shfl_xor_sync(0xffffffffu, tm0, 1));
        tm0 = fmaxf(tm0, __shfl_xor_sync(0xffffffffu, tm0, 2));
        tm1 = fmaxf(tm1, __shfl_xor_sync(0xffffffffu, tm1, 1));
        tm1 = fmaxf(tm1, __shfl_xor_sync(0xffffffffu, tm1, 2));

        const float mn0 = fmaxf(m0, tm0);
        const float mn1 = fmaxf(m1, tm1);
        const float al0 = __expf(m0 - mn0);
        const float al1 = __expf(m1 - mn1);
        m0 = mn0; m1 = mn1;

        float rs0 = 0.f, rs1 = 0.f;
        #pragma unroll
        for (int n = 0; n < 8; n++) {
            sacc[n][0] = __expf(sacc[n][0] - mn0);
            sacc[n][1] = __expf(sacc[n][1] - mn0);
            sacc[n][2] = __expf(sacc[n][2] - mn1);
            sacc[n][3] = __expf(sacc[n][3] - mn1);
            rs0 += sacc[n][0] + sacc[n][1];
            rs1 += sacc[n][2] + sacc[n][3];
        }
        rs0 += __shfl_xor_sync(0xffffffffu, rs0, 1);
        rs0 += __shfl_xor_sync(0xffffffffu, rs0, 2);
        rs1 += __shfl_xor_sync(0xffffffffu, rs1, 1);
        rs1 += __shfl_xor_sync(0xffffffffu, rs1, 2);
        l0 = l0 * al0 + rs0;
        l1 = l1 * al1 + rs1;

        // rescale running output accumulators
        #pragma unroll
        for (int n = 0; n < 16; n++) {
            oacc[n][0] *= al0; oacc[n][1] *= al0;
            oacc[n][2] *= al1; oacc[n][3] *= al1;
        }

        // ---- stage P (tf32) into warp-private smem rows ----
        #pragma unroll
        for (int n = 0; n < 8; n++) {
            float2 p01 = make_float2(to_tf32(sacc[n][0]), to_tf32(sacc[n][1]));
            float2 p23 = make_float2(to_tf32(sacc[n][2]), to_tf32(sacc[n][3]));
            *(float2*)(pb + (quad    ) * PSTR + n * 8 + 2 * qlan) = p01;
            *(float2*)(pb + (quad + 8) * PSTR + n * 8 + 2 * qlan) = p23;
        }
        __syncwarp();

        // ---- O += P * V : per-warp 16 x 128 ----
        #pragma unroll
        for (int k8 = 0; k8 < 8; k8++) {
            uint32_t a0 = __float_as_uint(pb[(quad    ) * PSTR + k8 * 8 + qlan    ]);
            uint32_t a1 = __float_as_uint(pb[(quad + 8) * PSTR + k8 * 8 + qlan    ]);
            uint32_t a2 = __float_as_uint(pb[(quad    ) * PSTR + k8 * 8 + qlan + 4]);
            uint32_t a3 = __float_as_uint(pb[(quad + 8) * PSTR + k8 * 8 + qlan + 4]);
            #pragma unroll
            for (int n = 0; n < 16; n++) {
                uint32_t b0 = __float_as_uint(sV[(k8 * 8 + qlan    ) * VSTR + n * 8 + quad]);
                uint32_t b1 = __float_as_uint(sV[(k8 * 8 + qlan + 4) * VSTR + n * 8 + quad]);
                mma_tf32(oacc[n], a0, a1, a2, a3, b0, b1);
            }
        }
        __syncwarp();   // P reads done before next tile overwrites pb
    }

    // ---- finalize: divide by l, store fp32 output ----
    const float inv0 = 1.f / l0;
    const float inv1 = 1.f / l1;
    const size_t orow0 = ((size_t)b * SEQQ + (size_t)qt * BQ + wid * 16 + quad) * HD;
    const size_t orow1 = orow0 + (size_t)8 * HD;
    #pragma unroll
    for (int n = 0; n < 16; n++) {
        int c = n * 8 + 2 * qlan;
        *(float2*)(Og + orow0 + c) = make_float2(oacc[n][0] * inv0, oacc[n][1] * inv0);
        *(float2*)(Og + orow1 + c) = make_float2(oacc[n][2] * inv1, oacc[n][3] * inv1);
    }
}

extern "C" void kernel_launch(void* const* d_in, const int* in_sizes, int n_in,
                              void* d_out, int out_size) {
    const float* Qg = (const float*)d_in[0];
    const float* Kg = (const float*)d_in[1];
    const float* Vg = (const float*)d_in[2];
    const int*   Lg = (const int*)d_in[3];
    float*       Og = (float*)d_out;

    const size_t smem_bytes = (size_t)SMEM_FLOATS * sizeof(float);
    cudaFuncSetAttribute(attn_tf32_kernel,
                         cudaFuncAttributeMaxDynamicSharedMemorySize,
                         (int)smem_bytes);

    dim3 grid(SEQQ / BQ, BATCH);   // (16, 16)
    attn_tf32_kernel<<<grid, NTHREADS, smem_bytes>>>(Qg, Kg, Vg, Lg, Og);
}

// round 7
// speedup vs baseline: 1.0025x; 1.0025x over previous
#include <cuda_runtime.h>
#include <cstdint>

// Problem constants
#define BATCH 16
#define SEQQ 2048
#define SEQK 2048
#define HD   128

// Tile config
#define BQ 128          // queries per CTA
#define BK 64           // keys per tile
#define NTHREADS 256    // 8 warps, 16 query rows per warp

// Shared-memory strides (floats), chosen for conflict-free fragment loads
#define QSTR 132        // 132 % 32 == 4  -> bank = 4*quad + qlan (perm)
#define KSTR 132
#define VSTR 136        // 136 % 32 == 8  -> bank = 8*qlan + quad (perm)
#define PSTR 68         // 68 % 32 == 4

#define SQ_OFF 0
#define SK_OFF (BQ*QSTR)                  // 16896
#define SV_OFF (SK_OFF + BK*KSTR)         // 25344
#define SP_OFF (SV_OFF + BK*VSTR)         // 34048
#define SMEM_FLOATS (SP_OFF + BQ*PSTR)    // 42752 floats = 171008 B

__device__ __forceinline__ float to_tf32(float x) {
    uint32_t u;
    asm("cvt.rna.tf32.f32 %0, %1;" : "=r"(u) : "f"(x));
    return __uint_as_float(u);
}

__device__ __forceinline__ void mma_tf32(float c[4],
                                         uint32_t a0, uint32_t a1, uint32_t a2, uint32_t a3,
                                         uint32_t b0, uint32_t b1) {
    asm volatile(
        "mma.sync.aligned.m16n8k8.row.col.f32.tf32.tf32.f32 "
        "{%0,%1,%2,%3}, {%4,%5,%6,%7}, {%8,%9}, {%0,%1,%2,%3};\n"
        : "+f"(c[0]), "+f"(c[1]), "+f"(c[2]), "+f"(c[3])
        : "r"(a0), "r"(a1), "r"(a2), "r"(a3), "r"(b0), "r"(b1));
}

extern __shared__ float smem[];

__global__ void __launch_bounds__(NTHREADS, 1)
attn_tf32_kernel(const float* __restrict__ Qg, const float* __restrict__ Kg,
                 const float* __restrict__ Vg, const int* __restrict__ Lg,
                 float* __restrict__ Og)
{
    const int b    = blockIdx.y;
    const int qt   = blockIdx.x;
    const int tid  = threadIdx.x;
    const int wid  = tid >> 5;
    const int lane = tid & 31;
    const int quad = lane >> 2;   // 0..7 (groupID)
    const int qlan = lane & 3;    // 0..3 (threadID_in_group)

    const int L = Lg[b];                       // >= 1 by construction
    const int ntiles = (L + BK - 1) / BK;

    float* sQ = smem + SQ_OFF;
    float* sK = smem + SK_OFF;
    float* sV = smem + SV_OFF;
    float* sP = smem + SP_OFF;

    const size_t baseQ  = ((size_t)b * SEQQ + (size_t)qt * BQ) * HD;
    const size_t baseKV = (size_t)b * SEQK * HD;
    const float scale = 0.08838834764831843f;  // 1/sqrt(128)

    // ---- load Q tile (BQ x HD), fold in softmax scale, round to tf32 ----
    for (int i = tid; i < BQ * (HD / 4); i += NTHREADS) {
        int row = i >> 5;     // HD/4 = 32
        int c4  = i & 31;
        float4 v = *(const float4*)(Qg + baseQ + (size_t)row * HD + c4 * 4);
        float* dst = sQ + row * QSTR + c4 * 4;
        dst[0] = to_tf32(v.x * scale);
        dst[1] = to_tf32(v.y * scale);
        dst[2] = to_tf32(v.z * scale);
        dst[3] = to_tf32(v.w * scale);
    }

    // per-thread softmax state: rows r0 = wid*16 + quad, r1 = r0 + 8
    float m0 = -1e30f, m1 = -1e30f;
    float l0 = 0.f,    l1 = 0.f;
    float oacc[16][4];
    #pragma unroll
    for (int n = 0; n < 16; n++) {
        oacc[n][0] = 0.f; oacc[n][1] = 0.f; oacc[n][2] = 0.f; oacc[n][3] = 0.f;
    }

    const float* qb = sQ + (wid * 16) * QSTR;
    float* pb = sP + (wid * 16) * PSTR;

    for (int t = 0; t < ntiles; ++t) {
        __syncthreads();   // previous tile fully consumed (sK/sV reusable)

        // ---- load K,V tile (BK x HD) with tf32 rounding ----
        const size_t kvoff = baseKV + (size_t)t * BK * HD;
        for (int i = tid; i < BK * (HD / 4); i += NTHREADS) {
            int row = i >> 5;
            int c4  = i & 31;
            float4 kv = *(const float4*)(Kg + kvoff + (size_t)row * HD + c4 * 4);
            float* dk = sK + row * KSTR + c4 * 4;
            dk[0] = to_tf32(kv.x); dk[1] = to_tf32(kv.y);
            dk[2] = to_tf32(kv.z); dk[3] = to_tf32(kv.w);
            float4 vv = *(const float4*)(Vg + kvoff + (size_t)row * HD + c4 * 4);
            float* dv = sV + row * VSTR + c4 * 4;
            dv[0] = to_tf32(vv.x); dv[1] = to_tf32(vv.y);
            dv[2] = to_tf32(vv.z); dv[3] = to_tf32(vv.w);
        }
        __syncthreads();

        // ---- S = Q * K^T : per-warp 16 x 64, tf32 MMA ----
        float sacc[8][4];
        #pragma unroll
        for (int n = 0; n < 8; n++) {
            sacc[n][0] = 0.f; sacc[n][1] = 0.f; sacc[n][2] = 0.f; sacc[n][3] = 0.f;
        }
        #pragma unroll
        for (int k8 = 0; k8 < 16; k8++) {
            uint32_t a0 = __float_as_uint(qb[(quad    ) * QSTR + k8 * 8 + qlan    ]);
            uint32_t a1 = __float_as_uint(qb[(quad + 8) * QSTR + k8 * 8 + qlan    ]);
            uint32_t a2 = __float_as_uint(qb[(quad    ) * QSTR + k8 * 8 + qlan + 4]);
            uint32_t a3 = __float_as_uint(qb[(quad + 8) * QSTR + k8 * 8 + qlan + 4]);
            #pragma unroll
            for (int n = 0; n < 8; n++) {
                uint32_t b0 = __float_as_uint(sK[(n * 8 + quad) * KSTR + k8 * 8 + qlan    ]);
                uint32_t b1 = __float_as_uint(sK[(n * 8 + quad) * KSTR + k8 * 8 + qlan + 4]);
                mma_tf32(sacc[n], a0, a1, a2, a3, b0, b1);
            }
        }

        // ---- mask trailing keys in the final (partial) tile ----
        const int lim = L - t * BK;
        if (lim < BK) {
            #pragma unroll
            for (int n = 0; n < 8; n++) {
                int c = n * 8 + 2 * qlan;
                if (c     >= lim) { sacc[n][0] = -1e30f; sacc[n][2] = -1e30f; }
                if (c + 1 >= lim) { sacc[n][1] = -1e30f; sacc[n][3] = -1e30f; }
            }
        }

        // ---- online softmax (rows r0, r1 per thread; quad = same rows) ----
        float tm0 = -1e30f, tm1 = -1e30f;
        #pragma unroll
        for (int n = 0; n < 8; n++) {
            tm0 = fmaxf(tm0, fmaxf(sacc[n][0], sacc[n][1]));
            tm1 = fmaxf(tm1, fmaxf(sacc[n][2], sacc[n][3]));
        }
        tm0 = fmaxf(tm0, __shfl_xor_sync(0xffffffffu, tm0, 1));
        tm0 = fmaxf(tm0, __shfl_xor_sync(0xffffffffu, tm0, 2));
        tm1 = fmaxf(tm1, __shfl_xor_sync(0xffffffffu, tm1, 1));
        tm1 = fmaxf(tm1, __shfl_xor_sync(0xffffffffu, tm1, 2));

        const float mn0 = fmaxf(m0, tm0);
        const float mn1 = fmaxf(m1, tm1);
        const float al0 = __expf(m0 - mn0);
        const float al1 = __expf(m1 - mn1);
        m0 = mn0; m1 = mn1;

        float rs0 = 0.f, rs1 = 0.f;
        #pragma unroll
        for (int n = 0; n < 8; n++) {
            sacc[n][0] = __expf(sacc[n][0] - mn0);
            sacc[n][1] = __expf(sacc[n][1] - mn0);
            sacc[n][2] = __expf(sacc[n][2] - mn1);
            sacc[n][3] = __expf(sacc[n][3] - mn1);
            rs0 += sacc[n][0] + sacc[n][1];
            rs1 += sacc[n][2] + sacc[n][3];
        }
        rs0 += __shfl_xor_sync(0xffffffffu, rs0, 1);
        rs0 += __shfl_xor_sync(0xffffffffu, rs0, 2);
        rs1 += __shfl_xor_sync(0xffffffffu, rs1, 1);
        rs1 += __shfl_xor_sync(0xffffffffu, rs1, 2);
        l0 = l0 * al0 + rs0;
        l1 = l1 * al1 + rs1;

        // rescale running output accumulators
        #pragma unroll
        for (int n = 0; n < 16; n++) {
            oacc[n][0] *= al0; oacc[n][1] *= al0;
            oacc[n][2] *= al1; oacc[n][3] *= al1;
        }

        // ---- stage P (tf32) into warp-private smem rows ----
        #pragma unroll
        for (int n = 0; n < 8; n++) {
            float2 p01 = make_float2(to_tf32(sacc[n][0]), to_tf32(sacc[n][1]));
            float2 p23 = make_float2(to_tf32(sacc[n][2]), to_tf32(sacc[n][3]));
            *(float2*)(pb + (quad    ) * PSTR + n * 8 + 2 * qlan) = p01;
            *(float2*)(pb + (quad + 8) * PSTR + n * 8 + 2 * qlan) = p23;
        }
        __syncwarp();

        // ---- O += P * V : per-warp 16 x 128 ----
        #pragma unroll
        for (int k8 = 0; k8 < 8; k8++) {
            uint32_t a0 = __float_as_uint(pb[(quad    ) * PSTR + k8 * 8 + qlan    ]);
            uint32_t a1 = __float_as_uint(pb[(quad + 8) * PSTR + k8 * 8 + qlan    ]);
            uint32_t a2 = __float_as_uint(pb[(quad    ) * PSTR + k8 * 8 + qlan + 4]);
            uint32_t a3 = __float_as_uint(pb[(quad + 8) * PSTR + k8 * 8 + qlan + 4]);
            #pragma unroll
            for (int n = 0; n < 16; n++) {
                uint32_t b0 = __float_as_uint(sV[(k8 * 8 + qlan    ) * VSTR + n * 8 + quad]);
                uint32_t b1 = __float_as_uint(sV[(k8 * 8 + qlan + 4) * VSTR + n * 8 + quad]);
                mma_tf32(oacc[n], a0, a1, a2, a3, b0, b1);
            }
        }
        __syncwarp();   // P reads done before next tile overwrites pb
    }

    // ---- finalize: divide by l, store fp32 output ----
    const float inv0 = 1.f / l0;
    const float inv1 = 1.f / l1;
    const size_t orow0 = ((size_t)b * SEQQ + (size_t)qt * BQ + wid * 16 + quad) * HD;
    const size_t orow1 = orow0 + (size_t)8 * HD;
    #pragma unroll
    for (int n = 0; n < 16; n++) {
        int c = n * 8 + 2 * qlan;
        *(float2*)(Og + orow0 + c) = make_float2(oacc[n][0] * inv0, oacc[n][1] * inv0);
        *(float2*)(Og + orow1 + c) = make_float2(oacc[n][2] * inv1, oacc[n][3] * inv1);
    }
}

extern "C" void kernel_launch(void* const* d_in, const int* in_sizes, int n_in,
                              void* d_out, int out_size) {
    const float* Qg = (const float*)d_in[0];
    const float* Kg = (const float*)d_in[1];
    const float* Vg = (const float*)d_in[2];
    const int*   Lg = (const int*)d_in[3];
    float*       Og = (float*)d_out;

    const size_t smem_bytes = (size_t)SMEM_FLOATS * sizeof(float);
    cudaFuncSetAttribute(attn_tf32_kernel,
                         cudaFuncAttributeMaxDynamicSharedMemorySize,
                         (int)smem_bytes);

    dim3 grid(SEQQ / BQ, BATCH);   // (16, 16)
    attn_tf32_kernel<<<grid, NTHREADS, smem_bytes>>>(Qg, Kg, Vg, Lg, Og);
}